// round 16
// baseline (speedup 1.0000x reference)
#include <cuda_runtime.h>
#include <cuda_fp16.h>
#include <cstdint>

// ---------------------------------------------------------------------------
// Scratch (device globals; allocations are forbidden).
// Constant operand images, fp16, row-major 64x64:
//   g_mrt : Mr^T [r][j]  (A of GEMM1')
//   g_mlt : Ml^T [l][i]  (A of GEMM2)
// ---------------------------------------------------------------------------
__device__ __align__(16) __half g_mrt[4096];
__device__ __align__(16) __half g_mlt[4096];

// ---------------------------------------------------------------------------
// Helpers
// ---------------------------------------------------------------------------
__device__ __forceinline__ uint32_t packh2(float a, float b) {
    __half2 h = __floats2half2_rn(a, b);
    return *reinterpret_cast<uint32_t*>(&h);
}

// mma.sync m16n8k16 fp16 -> f32 (baseline PTX, legal at sm_103).
__device__ __forceinline__ void mma_f16(float c[4], const uint32_t a[4],
                                        uint32_t b0, uint32_t b1) {
    asm volatile(
        "mma.sync.aligned.m16n8k16.row.col.f32.f16.f16.f32 "
        "{%0,%1,%2,%3}, {%4,%5,%6,%7}, {%8,%9}, {%0,%1,%2,%3};"
        : "+f"(c[0]), "+f"(c[1]), "+f"(c[2]), "+f"(c[3])
        : "r"(a[0]), "r"(a[1]), "r"(a[2]), "r"(a[3]), "r"(b0), "r"(b1));
}

// ---------------------------------------------------------------------------
// Setup kernel: one warp per output column.
//   m_left[:,c]  -> g_mlt row c ;  m_right[:,c] -> g_mrt row c
//   m[:,c] = Qu * (diag .* (Qv * e_c)),  Q*y = (I-B)^{-1}(I+B) y via the
//   fixpoint q <- rhs + B q  (||B|| ~ 0.16; NIT=10 -> err ~2e-9).
// Grid: 32 CTAs x 128 thr.  CTA b: side = b>>4, columns c = (b&15)*4 + warp.
// B^T staged pad-65 (Bt[j*65+i] = B[i][j]): coalesced stage, conflict-free
// matvec reads (lane rows i0=2*lane, i1=2*lane+1).
// ---------------------------------------------------------------------------
#define NIT 10

__global__ void __launch_bounds__(128)
setup_kernel(const float* __restrict__ ul, const float* __restrict__ vl,
             const float* __restrict__ dl, const float* __restrict__ ur,
             const float* __restrict__ vr, const float* __restrict__ dr) {
    __shared__ float But[64 * 65], Bvt[64 * 65];
    __shared__ float qbuf[4][64];
    const int tid = threadIdx.x;
    const int w = tid >> 5, lane = tid & 31;
    const int side = blockIdx.x >> 4;
    const int c = (blockIdx.x & 15) * 4 + w;
    const float* u  = side ? ur : ul;
    const float* v  = side ? vr : vl;
    const float* dg = side ? dr : dl;

    // Stage B^T images: B = 0.5 * (tril(X,-1) - tril(X,-1)^T).
    for (int e = tid; e < 4096; e += 128) {
        const int i = e >> 6, j = e & 63;
        float bu = 0.f, bv = 0.f;
        if (i > j)      { bu =  0.5f * u[i * 64 + j]; bv =  0.5f * v[i * 64 + j]; }
        else if (i < j) { bu = -0.5f * u[j * 64 + i]; bv = -0.5f * v[j * 64 + i]; }
        But[j * 65 + i] = bu;
        Bvt[j * 65 + i] = bv;
    }
    __syncthreads();

    const int i0 = 2 * lane, i1 = i0 + 1;
    float* q = qbuf[w];

    // ---- solve (I-Bv) y = (I+Bv) e_c ----
    const float rv0 = (i0 == c ? 1.f : 0.f) + Bvt[c * 65 + i0];
    const float rv1 = (i1 == c ? 1.f : 0.f) + Bvt[c * 65 + i1];
    q[i0] = rv0; q[i1] = rv1; __syncwarp();
    #pragma unroll 1
    for (int it = 0; it < NIT; it++) {
        float a0 = 0, b0 = 0, a1 = 0, b1 = 0;
        #pragma unroll 8
        for (int j = 0; j < 64; j += 2) {
            const float qa = q[j], qb = q[j + 1];
            a0 += Bvt[j * 65 + i0] * qa;        a1 += Bvt[j * 65 + i1] * qa;
            b0 += Bvt[(j + 1) * 65 + i0] * qb;  b1 += Bvt[(j + 1) * 65 + i1] * qb;
        }
        __syncwarp();
        q[i0] = rv0 + a0 + b0; q[i1] = rv1 + a1 + b1;
        __syncwarp();
    }

    // ---- w = diag .* y ----
    const float w0 = dg[i0] * q[i0], w1 = dg[i1] * q[i1];
    __syncwarp(); q[i0] = w0; q[i1] = w1; __syncwarp();

    // ---- z = (I+Bu) w ----
    float z0 = w0, z1 = w1;
    #pragma unroll 8
    for (int j = 0; j < 64; j++) {
        const float qj = q[j];
        z0 += But[j * 65 + i0] * qj; z1 += But[j * 65 + i1] * qj;
    }
    __syncwarp(); q[i0] = z0; q[i1] = z1; __syncwarp();

    // ---- solve (I-Bu) p = z ----
    #pragma unroll 1
    for (int it = 0; it < NIT; it++) {
        float a0 = 0, b0 = 0, a1 = 0, b1 = 0;
        #pragma unroll 8
        for (int j = 0; j < 64; j += 2) {
            const float qa = q[j], qb = q[j + 1];
            a0 += But[j * 65 + i0] * qa;        a1 += But[j * 65 + i1] * qa;
            b0 += But[(j + 1) * 65 + i0] * qb;  b1 += But[(j + 1) * 65 + i1] * qb;
        }
        __syncwarp();
        q[i0] = z0 + a0 + b0; q[i1] = z1 + a1 + b1;
        __syncwarp();
    }

    // Row c of the transposed image = column c of m.
    uint32_t* dst = (uint32_t*)(side ? g_mrt : g_mlt);
    dst[c * 32 + lane] = packh2(q[i0], q[i1]);
}

// ---------------------------------------------------------------------------
// Tile kernel: pure-fp16 mma.sync, register-chained.  CTA = 8 warps, 4 tiles,
// ALL staged upfront (one __syncthreads; both mma passes sync-free).
// Warp w: tile-group tt = w>>2, r-slab s = w&3 (r in [16s,16s+16)).
//   GEMM1': C1T = Mrt(A, m=r) x X(B, n=i, col-major-k = X row-major)
//   pack:   __floats2half2_rn(c0,c1) IS the GEMM2 B-frag -- C1 stays in regs.
//   GEMM2:  O = Mlt(A, m=l) x C1(B from regs).
// ---------------------------------------------------------------------------
#define PADB   144                 // bytes per 64-fp16 row (72 fp16)
#define MATB   (64 * PADB)         // 9216
#define MRT_H  0
#define MLT_H  (MATB)
#define XBASE  (2 * MATB)          // X: tile t -> XBASE + t*MATB
#define SMEM_SZ (6 * MATB)         // 55296

__global__ void __launch_bounds__(256, 3)
tile_kernel(const float* __restrict__ x,
            const float* __restrict__ dsc,
            float* __restrict__ out) {
    extern __shared__ char sm[];
    const int tid = threadIdx.x;
    const int wid = tid >> 5, lane = tid & 31;
    const int g = lane >> 2, tg = lane & 3;
    const int tt = wid >> 2, s = wid & 3;
    const int slab = s * 16;

    // Constants -> smem with pad re-stride (2048 u32 words per matrix).
    for (int q = tid; q < 2048; q += 256) {
        const int row = q >> 5, cw = q & 31;
        const int d = row * 36 + cw;
        ((uint32_t*)(sm + MRT_H))[d] = ((const uint32_t*)g_mrt)[q];
        ((uint32_t*)(sm + MLT_H))[d] = ((const uint32_t*)g_mlt)[q];
    }

    // diag_scale in registers, reused for all 4 tiles.
    const float4* dsc4 = (const float4*)dsc;
    float4 dreg[4];
    #pragma unroll
    for (int v = 0; v < 4; v++) dreg[v] = dsc4[v * 256 + tid];

    const size_t cbase = (size_t)blockIdx.x * 4 * 4096;

    // Stage ALL 4 tiles' X: scale, round to fp16, padded row-major.
    #pragma unroll
    for (int st = 0; st < 4; st++) {
        const int xh = XBASE + st * MATB;
        const float4* xt = (const float4*)(x + cbase + st * 4096);
        #pragma unroll
        for (int v = 0; v < 4; v++) {
            const int idx = v * 256 + tid;
            float4 xv = xt[idx];
            const float4 dv = dreg[v];
            uint32_t h01 = packh2(xv.x * dv.x, xv.y * dv.y);
            uint32_t h23 = packh2(xv.z * dv.z, xv.w * dv.w);
            const int e = idx * 4, i = e >> 6, j = e & 63;
            *(uint2*)(sm + xh + i * PADB + j * 2) = make_uint2(h01, h23);
        }
    }
    __syncthreads();   // the only block-wide sync

    #pragma unroll 1
    for (int pass = 0; pass < 2; pass++) {
        const int tile = pass * 2 + tt;
        const int xb = XBASE + tile * MATB;

        // ---- GEMM1': C1T[r][i] = sum_j Mrt[r][j] * X[i][j] ----
        float c1t[8][4] = {};
        #pragma unroll
        for (int kt = 0; kt < 4; kt++) {
            const int kb = kt * 32 + tg * 4;
            uint32_t am[4] = {
                *(const uint32_t*)(sm + MRT_H + (slab + g) * PADB + kb),
                *(const uint32_t*)(sm + MRT_H + (slab + 8 + g) * PADB + kb),
                *(const uint32_t*)(sm + MRT_H + (slab + g) * PADB + kb + 16),
                *(const uint32_t*)(sm + MRT_H + (slab + 8 + g) * PADB + kb + 16) };
            #pragma unroll
            for (int nt = 0; nt < 8; nt++) {
                const int bbase = xb + (8 * nt + g) * PADB + kb;
                uint32_t b0 = *(const uint32_t*)(sm + bbase);
                uint32_t b1 = *(const uint32_t*)(sm + bbase + 16);
                mma_f16(c1t[nt], am, b0, b1);
            }
        }

        // Pack C1T C-frags into GEMM2 B-frags (registers only).
        uint32_t bf[4][2][2];
        #pragma unroll
        for (int kt = 0; kt < 4; kt++) {
            bf[kt][0][0] = packh2(c1t[2 * kt][0],     c1t[2 * kt][1]);
            bf[kt][0][1] = packh2(c1t[2 * kt + 1][0], c1t[2 * kt + 1][1]);
            bf[kt][1][0] = packh2(c1t[2 * kt][2],     c1t[2 * kt][3]);
            bf[kt][1][1] = packh2(c1t[2 * kt + 1][2], c1t[2 * kt + 1][3]);
        }

        // ---- GEMM2: O[l][r] = sum_i Mlt[l][i] * C1[i][r] ----
        float acc2[2][4][4] = {};
        #pragma unroll
        for (int kt = 0; kt < 4; kt++) {
            const int kb = kt * 32 + tg * 4;
            #pragma unroll
            for (int mt = 0; mt < 4; mt++) {
                uint32_t am[4] = {
                    *(const uint32_t*)(sm + MLT_H + (mt * 16 + g) * PADB + kb),
                    *(const uint32_t*)(sm + MLT_H + (mt * 16 + 8 + g) * PADB + kb),
                    *(const uint32_t*)(sm + MLT_H + (mt * 16 + g) * PADB + kb + 16),
                    *(const uint32_t*)(sm + MLT_H + (mt * 16 + 8 + g) * PADB + kb + 16) };
                #pragma unroll
                for (int nb = 0; nb < 2; nb++)
                    mma_f16(acc2[nb][mt], am, bf[kt][nb][0], bf[kt][nb][1]);
            }
        }

        // Store O: l = 16mt + g (+8), r = slab + nb*8 + 2tg (+1).
        {
            float* ob = out + cbase + tile * 4096;
            #pragma unroll
            for (int nb = 0; nb < 2; nb++) {
                const int r0 = slab + nb * 8 + tg * 2;
                #pragma unroll
                for (int mt = 0; mt < 4; mt++) {
                    const int l0 = mt * 16 + g;
                    *(float2*)(ob + l0 * 64 + r0) =
                        make_float2(acc2[nb][mt][0], acc2[nb][mt][1]);
                    *(float2*)(ob + (l0 + 8) * 64 + r0) =
                        make_float2(acc2[nb][mt][2], acc2[nb][mt][3]);
                }
            }
        }
    }
}

// ---------------------------------------------------------------------------
// Launch.  Inputs: x, u_left, v_left, diag_left, u_right, v_right, diag_right,
// diag_scale.  Output float32.
// ---------------------------------------------------------------------------
extern "C" void kernel_launch(void* const* d_in, const int* in_sizes, int n_in,
                              void* d_out, int out_size) {
    const float* x   = (const float*)d_in[0];
    const float* ul  = (const float*)d_in[1];
    const float* vl  = (const float*)d_in[2];
    const float* dl  = (const float*)d_in[3];
    const float* ur  = (const float*)d_in[4];
    const float* vr  = (const float*)d_in[5];
    const float* dr  = (const float*)d_in[6];
    const float* dsc = (const float*)d_in[7];
    float* out = (float*)d_out;

    const int ntile = in_sizes[0] / 4096;   // 8192

    cudaFuncSetAttribute(tile_kernel, cudaFuncAttributeMaxDynamicSharedMemorySize, SMEM_SZ);

    setup_kernel<<<32, 128>>>(ul, vl, dl, ur, vr, dr);
    tile_kernel<<<ntile / 4, 256, SMEM_SZ>>>(x, dsc, out);
}